// round 8
// baseline (speedup 1.0000x reference)
#include <cuda_runtime.h>

// L1Loss: out = mean(|yhat - y|) over 64*128*4096 fp32 elements.
// R8: R7 (fused single-atomic epilogue) + __ldcs streaming loads.
// Data is read exactly once -> evict-first hints cut L1/L2 allocation churn.

#define NBLOCKS 2368
#define NTHREADS 256
#define FIX_SCALE 1048576.0   // 2^20

__device__ unsigned long long g_pack = 0ull;  // reset by last block each call

__global__ void __launch_bounds__(NTHREADS) l1_reduce_kernel(
    const float4* __restrict__ a,
    const float4* __restrict__ b,
    float* __restrict__ out,
    int n4,            // number of float4 elements
    int n_tail,        // scalar elements after n4*4
    float inv_n)
{
    float acc = 0.0f;

    const int idx    = blockIdx.x * blockDim.x + threadIdx.x;
    const int stride = gridDim.x * blockDim.x;

    for (int i = idx; i < n4; i += stride) {
        float4 x = __ldcs(&a[i]);
        float4 y = __ldcs(&b[i]);
        acc += fabsf(x.x - y.x);
        acc += fabsf(x.y - y.y);
        acc += fabsf(x.z - y.z);
        acc += fabsf(x.w - y.w);
    }

    // Scalar tail (N not divisible by 4)
    if (blockIdx.x == 0 && threadIdx.x < n_tail) {
        const float* af = (const float*)a;
        const float* bf = (const float*)b;
        int t = n4 * 4 + threadIdx.x;
        acc += fabsf(af[t] - bf[t]);
    }

    // Intra-block reduction
    #pragma unroll
    for (int o = 16; o > 0; o >>= 1)
        acc += __shfl_down_sync(0xffffffffu, acc, o);

    __shared__ float smem[NTHREADS / 32];
    int lane = threadIdx.x & 31;
    int wid  = threadIdx.x >> 5;
    if (lane == 0) smem[wid] = acc;
    __syncthreads();
    // Warps 1..7 (and warp 0 lanes 1..31) exit after this point.

    if (threadIdx.x == 0) {
        float v = 0.0f;
        #pragma unroll
        for (int w = 0; w < NTHREADS / 32; w++) v += smem[w];

        // Fixed-point encode: partial in 2^-20 units, count=1 in low 12 bits.
        unsigned long long fixed =
            (unsigned long long)__double2ll_rn((double)v * FIX_SCALE);
        unsigned long long pack = (fixed << 12) | 1ull;

        unsigned long long old = atomicAdd(&g_pack, pack);

        if ((old & 0xFFFull) == (unsigned long long)(NBLOCKS - 1)) {
            // We are the last block; total = old + our contribution.
            unsigned long long total_fixed = (old + pack) >> 12;
            double total = (double)(long long)total_fixed * (1.0 / FIX_SCALE);
            out[0] = (float)(total * (double)inv_n);
            g_pack = 0ull;   // reset for next graph replay (all peers done)
        }
    }
}

extern "C" void kernel_launch(void* const* d_in, const int* in_sizes, int n_in,
                              void* d_out, int out_size)
{
    const float* yhat = (const float*)d_in[0];
    const float* y    = (const float*)d_in[1];
    float* out = (float*)d_out;

    long long n = in_sizes[0];
    int n4 = (int)(n / 4);
    int n_tail = (int)(n - (long long)n4 * 4);
    float inv_n = 1.0f / (float)n;

    l1_reduce_kernel<<<NBLOCKS, NTHREADS>>>(
        (const float4*)yhat, (const float4*)y, out, n4, n_tail, inv_n);
}

// round 9
// speedup vs baseline: 1.0241x; 1.0241x over previous
#include <cuda_runtime.h>

// L1Loss: out = mean(|yhat - y|) over 64*128*4096 fp32 elements.
// R9: 256-bit streaming loads (sm_100+ ld.global.cs.v8.f32) + R7 fused
// single-atomic epilogue. Halves LDG count per byte vs float4.

#define NBLOCKS 2368
#define NTHREADS 256
#define FIX_SCALE 1048576.0   // 2^20

__device__ unsigned long long g_pack = 0ull;  // reset by last block each call

struct __align__(32) f8 { float v[8]; };

__device__ __forceinline__ f8 ldcs256(const float* p) {
    f8 r;
    asm volatile(
        "ld.global.cs.v8.f32 {%0,%1,%2,%3,%4,%5,%6,%7}, [%8];"
        : "=f"(r.v[0]), "=f"(r.v[1]), "=f"(r.v[2]), "=f"(r.v[3]),
          "=f"(r.v[4]), "=f"(r.v[5]), "=f"(r.v[6]), "=f"(r.v[7])
        : "l"(p));
    return r;
}

__global__ void __launch_bounds__(NTHREADS) l1_reduce_kernel(
    const float* __restrict__ a,
    const float* __restrict__ b,
    float* __restrict__ out,
    int n8,            // number of float8 groups
    int n_tail,        // scalar elements after n8*8
    float inv_n)
{
    float acc = 0.0f;

    const int idx    = blockIdx.x * blockDim.x + threadIdx.x;
    const int stride = gridDim.x * blockDim.x;

    for (int i = idx; i < n8; i += stride) {
        f8 x = ldcs256(a + (size_t)i * 8);
        f8 y = ldcs256(b + (size_t)i * 8);
        #pragma unroll
        for (int k = 0; k < 8; k++)
            acc += fabsf(x.v[k] - y.v[k]);
    }

    // Scalar tail (N not divisible by 8)
    if (blockIdx.x == 0 && threadIdx.x < n_tail) {
        int t = n8 * 8 + threadIdx.x;
        acc += fabsf(a[t] - b[t]);
    }

    // Intra-block reduction
    #pragma unroll
    for (int o = 16; o > 0; o >>= 1)
        acc += __shfl_down_sync(0xffffffffu, acc, o);

    __shared__ float smem[NTHREADS / 32];
    int lane = threadIdx.x & 31;
    int wid  = threadIdx.x >> 5;
    if (lane == 0) smem[wid] = acc;
    __syncthreads();
    // Warps 1..7 (and warp 0 lanes 1..31) exit after this point.

    if (threadIdx.x == 0) {
        float v = 0.0f;
        #pragma unroll
        for (int w = 0; w < NTHREADS / 32; w++) v += smem[w];

        // Fixed-point encode: partial in 2^-20 units, count=1 in low 12 bits.
        unsigned long long fixed =
            (unsigned long long)__double2ll_rn((double)v * FIX_SCALE);
        unsigned long long pack = (fixed << 12) | 1ull;

        unsigned long long old = atomicAdd(&g_pack, pack);

        if ((old & 0xFFFull) == (unsigned long long)(NBLOCKS - 1)) {
            // We are the last block; total = old + our contribution.
            unsigned long long total_fixed = (old + pack) >> 12;
            double total = (double)(long long)total_fixed * (1.0 / FIX_SCALE);
            out[0] = (float)(total * (double)inv_n);
            g_pack = 0ull;   // reset for next graph replay (all peers done)
        }
    }
}

extern "C" void kernel_launch(void* const* d_in, const int* in_sizes, int n_in,
                              void* d_out, int out_size)
{
    const float* yhat = (const float*)d_in[0];
    const float* y    = (const float*)d_in[1];
    float* out = (float*)d_out;

    long long n = in_sizes[0];
    int n8 = (int)(n / 8);
    int n_tail = (int)(n - (long long)n8 * 8);
    float inv_n = 1.0f / (float)n;

    l1_reduce_kernel<<<NBLOCKS, NTHREADS>>>(yhat, y, out, n8, n_tail, inv_n);
}